// round 11
// baseline (speedup 1.0000x reference)
#include <cuda_runtime.h>
#include <cstddef>

// GazeLSTM on GB300 (sm_103a). B=16384, T=128, half=64.
// Back blocks (128 thr, 32 b's): 4-segment parallel scan of the backward chain
//   w0: seg0 vectors (t 0..15) + fused LSTM (all weights in volatile smem)
//   w1: seg1 matrix product M1, then vector replay t 16..31
//   w2: seg2 matrix product M2, then vector replay t 32..47
//   w3: idle phase1; prefix u3 = M2*M1*v15; replay t 48..63; writes rows 0..15
// Fwd blocks (128 thr, 128 b's): 4 independent proven forward-chain warps.

#define BT 32       // b's per warp
#define CW 4        // matrices per chunk
#define NQ 9        // float4 per b per chunk (4*9 floats)

#define STG_OFF 0       // 3 staging slots x (2 x 4608 B) = 27648
#define XR_OFF  27648   // dirs ring: 192 rows x 32 floats = 24576
#define MM_OFF  52224   // M1,M2: 2 x 9 x 32 floats = 2304
#define SW_OFF  54528   // LSTM weights: 42 u64 = 336
#define SMEM_DYN 55296

__device__ __forceinline__ unsigned long long pk2(float lo, float hi) {
    unsigned long long r; asm("mov.b64 %0, {%1, %2};" : "=l"(r) : "f"(lo), "f"(hi)); return r;
}
__device__ __forceinline__ void upk2(float& lo, float& hi, unsigned long long v) {
    asm("mov.b64 {%0, %1}, %2;" : "=f"(lo), "=f"(hi) : "l"(v));
}
__device__ __forceinline__ unsigned long long fma2(unsigned long long a, unsigned long long b, unsigned long long c) {
    unsigned long long d; asm("fma.rn.f32x2 %0, %1, %2, %3;" : "=l"(d) : "l"(a), "l"(b), "l"(c)); return d;
}
__device__ __forceinline__ float tanhx(float x) {
    float y; asm("tanh.approx.f32 %0, %1;" : "=f"(y) : "f"(x)); return y;
}

#define CP16(dst_u32, src_ptr) \
    asm volatile("cp.async.cg.shared.global [%0], [%1], 16;" :: "r"(dst_u32), "l"(src_ptr))
#define CP_COMMIT() asm volatile("cp.async.commit_group;")
#define CP_WAIT1()  asm volatile("cp.async.wait_group 1;")
#define CP_WAIT0()  asm volatile("cp.async.wait_group 0;")

// Stage one C=4 chunk (32 b x 9 quads), 9 CP16/thread. j0 % 4 == 0 required.
__device__ __forceinline__ void stage4(float4* __restrict__ sdst,
                                       const float4* __restrict__ src4base,
                                       int t9q, int lane) {
    int bp = lane / NQ, q = lane - bp * NQ;
#pragma unroll
    for (int k = 0; k < NQ; k++) {
        const float4* src = src4base + (size_t)bp * t9q + q;
        unsigned dst = (unsigned)__cvta_generic_to_shared(sdst + q * BT + (bp ^ q));
        CP16(dst, src);
        q += 5; bp += 3;                  // 32 = 3*9 + 5
        if (q >= NQ) { q -= NQ; bp += 1; }
    }
}

template <int M>
__device__ __forceinline__ void loadA4(float* A, const float4* __restrict__ buf, int lane) {
    constexpr int F0 = 9 * M, QA = F0 >> 2, OFF = F0 & 3;
    float tmp[12];
    *(float4*)(tmp + 0) = buf[(QA + 0) * BT + (lane ^ (QA + 0))];
    *(float4*)(tmp + 4) = buf[(QA + 1) * BT + (lane ^ (QA + 1))];
    *(float4*)(tmp + 8) = buf[(QA + 2) * BT + (lane ^ (QA + 2))];
#pragma unroll
    for (int i = 0; i < 9; i++) A[i] = tmp[OFF + i];
}

// Coalesced writeback: NF floats/b for 32 b's from swizzled sout (row r = bank ^ r).
template <int NF>
__device__ __forceinline__ void store_chain(float* __restrict__ gdst, size_t T3,
                                            const float* __restrict__ sout, int lane) {
    int bp = lane / NF, e = lane - bp * NF;
    constexpr int DB = BT / NF, DE = BT % NF;
#pragma unroll
    for (int k = 0; k < NF; k++) {
        gdst[(size_t)bp * T3 + e] = sout[e * BT + (bp ^ (e & 31))];
        bp += DB; e += DE;
        if (e >= NF) { e -= NF; bp += 1; }
    }
}

// Writeback 16 rows (48 floats/b) from xr with global-row swizzle offset ro.
__device__ __forceinline__ void storeX48(float* __restrict__ gdst, size_t T3,
                                         const float* __restrict__ xrseg, int ro, int lane) {
    int bp = 0, e = lane;                 // lane < 48
#pragma unroll
    for (int k = 0; k < 48; k++) {
        gdst[(size_t)bp * T3 + e] = xrseg[e * BT + (bp ^ ((e + ro) & 31))];
        e += 32;
        if (e >= 48) { e -= 48; bp += 1; }
    }
}

// LSTM step, all weights from volatile smem (prescaled: sigmoid gates x0.5).
#define LSTM_STEP_SW(x0, x1, x2)                                                     \
    do {                                                                             \
        unsigned long long xx0 = pk2((x0), (x0)), xx1 = pk2((x1), (x1)), xx2 = pk2((x2), (x2)); \
        unsigned long long hh0 = pk2(h0, h0), hh1 = pk2(h1, h1), hh2 = pk2(h2, h2);  \
        float th[12];                                                                \
        _Pragma("unroll") for (int p = 0; p < 6; p++) {                              \
            unsigned long long xp = fma2(vw[p*7+0], xx0, fma2(vw[p*7+1], xx1, fma2(vw[p*7+2], xx2, vw[p*7+6]))); \
            unsigned long long g  = fma2(vw[p*7+3], hh0, fma2(vw[p*7+4], hh1, fma2(vw[p*7+5], hh2, xp)));        \
            float a_, b_; upk2(a_, b_, g);                                           \
            th[2*p] = tanhx(a_); th[2*p+1] = tanhx(b_);                              \
        }                                                                            \
        float i0 = fmaf(0.5f, th[0], 0.5f), i1 = fmaf(0.5f, th[1], 0.5f), i2 = fmaf(0.5f, th[2], 0.5f); \
        float f0 = fmaf(0.5f, th[3], 0.5f), f1 = fmaf(0.5f, th[4], 0.5f), f2 = fmaf(0.5f, th[5], 0.5f); \
        float o0 = fmaf(0.5f, th[9], 0.5f), o1 = fmaf(0.5f, th[10], 0.5f), o2 = fmaf(0.5f, th[11], 0.5f); \
        c0 = fmaf(f0, c0, i0 * th[6]);                                               \
        c1 = fmaf(f1, c1, i1 * th[7]);                                               \
        c2 = fmaf(f2, c2, i2 * th[8]);                                               \
        h0 = o0 * tanhx(c0); h1 = o1 * tanhx(c1); h2 = o2 * tanhx(c2);               \
    } while (0)

__global__ __launch_bounds__(128, 4) void gaze_kernel(
    const float* __restrict__ dir, const float* __restrict__ R,
    const float* __restrict__ Wih, const float* __restrict__ Whh,
    const float* __restrict__ bih, const float* __restrict__ bhh,
    float* __restrict__ out, int B, int T, int nbackblk)
{
    extern __shared__ char smem[];
    const int half = T >> 1;
    const int t9q = (T * 9) >> 2;
    const size_t T3 = (size_t)T * 3;
    const int tid = threadIdx.x;
    const int lane = tid & 31;
    const int w = tid >> 5;

    if ((int)blockIdx.x < nbackblk) {
        // ================= BACK block: 32 b's, 4-segment scan =================
        const int bbase = blockIdx.x * BT;
        const float4* R4 = (const float4*)R + (size_t)bbase * t9q;
        float* oblk = out + (size_t)bbase * T3;
        float* xr = (float*)(smem + XR_OFF);
        float* mm = (float*)(smem + MM_OFF);
        const int slot = (w == 3) ? 0 : w;
        float4* buf0 = (float4*)(smem + STG_OFF + slot * 9216);
        float4* buf1 = buf0 + CW * NQ * BT / CW;   // +288 quads = 4608 B
        float4* bufs[2] = { buf0, buf1 };

        if (w == 3 && lane < 6) {   // LSTM weights -> smem (prescaled, packed)
            unsigned long long* sw = (unsigned long long*)(smem + SW_OFF);
            const int p = lane, g0 = 2 * p, g1 = 2 * p + 1;
            const float s0 = (g0 >= 6 && g0 <= 8) ? 1.0f : 0.5f;
            const float s1 = (g1 >= 6 && g1 <= 8) ? 1.0f : 0.5f;
#pragma unroll
            for (int j = 0; j < 3; j++) {
                sw[p*7 + j]     = pk2(__ldg(Wih + g0*3 + j) * s0, __ldg(Wih + g1*3 + j) * s1);
                sw[p*7 + 3 + j] = pk2(__ldg(Whh + g0*3 + j) * s0, __ldg(Whh + g1*3 + j) * s1);
            }
            sw[p*7 + 6] = pk2((__ldg(bih + g0) + __ldg(bhh + g0)) * s0,
                              (__ldg(bih + g1) + __ldg(bhh + g1)) * s1);
        }

        if (w == 0) {
            // ---- seg0 vectors (t = 0..15, j = 63-t) + fused LSTM ----
            const float d0 = __ldg(dir + (size_t)(bbase + lane) * 3 + 0);
            const float d1 = __ldg(dir + (size_t)(bbase + lane) * 3 + 1);
            const float d2 = __ldg(dir + (size_t)(bbase + lane) * 3 + 2);
            float v0 = d0, v1 = d1, v2 = d2;

            stage4(bufs[0], R4 + ((60 * 9) >> 2), t9q, lane); CP_COMMIT();
            for (int cc = 0; cc < 4; cc++) {
                if (cc < 3) { stage4(bufs[(cc+1)&1], R4 + (((60 - 4*(cc+1)) * 9) >> 2), t9q, lane); CP_COMMIT(); CP_WAIT1(); }
                else CP_WAIT0();
                __syncwarp();
                const float4* buf = bufs[cc & 1];
#pragma unroll
                for (int sub = 0; sub < 4; sub++) {
                    float A[9];
                    switch (sub) {                 // j descending: loadA<3-sub>
                        case 0: loadA4<3>(A, buf, lane); break;
                        case 1: loadA4<2>(A, buf, lane); break;
                        case 2: loadA4<1>(A, buf, lane); break;
                        default: loadA4<0>(A, buf, lane); break;
                    }
                    float n0 = fmaf(A[6], v2, fmaf(A[3], v1, A[0] * v0));
                    float n1 = fmaf(A[7], v2, fmaf(A[4], v1, A[1] * v0));
                    float n2 = fmaf(A[8], v2, fmaf(A[5], v1, A[2] * v0));
                    v0 = n0; v1 = n1; v2 = n2;
                    const int r = 3 * (4*cc + sub);
                    xr[(r+0) * BT + (lane ^ ((r+0) & 31))] = v0;
                    xr[(r+1) * BT + (lane ^ ((r+1) & 31))] = v1;
                    xr[(r+2) * BT + (lane ^ ((r+2) & 31))] = v2;
                }
            }
            __syncthreads();   // sync1: xr 0..47, M1/M2, weights ready

            const volatile unsigned long long* vw = (const volatile unsigned long long*)(smem + SW_OFF);
            float h0 = 0.f, h1 = 0.f, h2 = 0.f, c0 = 0.f, c1 = 0.f, c2 = 0.f;
#pragma unroll 2
            for (int t = 0; t < 16; t++) {
                const int r = 3 * t;
                float x0 = xr[(r+0) * BT + (lane ^ ((r+0) & 31))];
                float x1 = xr[(r+1) * BT + (lane ^ ((r+1) & 31))];
                float x2 = xr[(r+2) * BT + (lane ^ ((r+2) & 31))];
                LSTM_STEP_SW(x0, x1, x2);
            }
            __syncthreads();   // sync2: xr 48..191 ready
#pragma unroll 2
            for (int t = 16; t < 64; t++) {
                const int r = 3 * t;
                float x0 = xr[(r+0) * BT + (lane ^ ((r+0) & 31))];
                float x1 = xr[(r+1) * BT + (lane ^ ((r+1) & 31))];
                float x2 = xr[(r+2) * BT + (lane ^ ((r+2) & 31))];
                LSTM_STEP_SW(x0, x1, x2);
            }
            LSTM_STEP_SW(d0, d1, d2);
            float* ob = out + (size_t)(bbase + lane) * T3 + (size_t)half * 3;
            ob[0] = h0; ob[1] = h1; ob[2] = h2;
        } else if (w < 3) {
            // ---- seg w matrix product, then replay ----
            const int s = w;
            const int jb = 60 - 16 * s;            // chunk cc: j0 = jb - 4cc
            float M[9] = {1.f,0.f,0.f, 0.f,1.f,0.f, 0.f,0.f,1.f};

            stage4(bufs[0], R4 + ((jb * 9) >> 2), t9q, lane); CP_COMMIT();
            for (int cc = 0; cc < 4; cc++) {
                if (cc < 3) { stage4(bufs[(cc+1)&1], R4 + (((jb - 4*(cc+1)) * 9) >> 2), t9q, lane); CP_COMMIT(); CP_WAIT1(); }
                else CP_WAIT0();
                __syncwarp();
                const float4* buf = bufs[cc & 1];
#pragma unroll
                for (int sub = 0; sub < 4; sub++) {
                    float A[9];
                    switch (sub) {
                        case 0: loadA4<3>(A, buf, lane); break;
                        case 1: loadA4<2>(A, buf, lane); break;
                        case 2: loadA4<1>(A, buf, lane); break;
                        default: loadA4<0>(A, buf, lane); break;
                    }
                    // M <- A^T * M
                    float NM[9];
#pragma unroll
                    for (int r = 0; r < 3; r++)
#pragma unroll
                        for (int c = 0; c < 3; c++)
                            NM[r*3+c] = fmaf(A[6+r], M[6+c], fmaf(A[3+r], M[3+c], A[r] * M[c]));
#pragma unroll
                    for (int i = 0; i < 9; i++) M[i] = NM[i];
                }
            }
#pragma unroll
            for (int e = 0; e < 9; e++) mm[(s-1) * 9 * BT + e * BT + lane] = M[e];
            __syncthreads();   // sync1

            // prefix vector u_s
            float u0 = xr[45 * BT + (lane ^ 13)];
            float u1 = xr[46 * BT + (lane ^ 14)];
            float u2 = xr[47 * BT + (lane ^ 15)];
            if (s == 2) {      // u2seg = M1 * v15
                const float* m1 = mm;
                float t0 = fmaf(m1[2*BT+lane], u2, fmaf(m1[1*BT+lane], u1, m1[0*BT+lane] * u0));
                float t1 = fmaf(m1[5*BT+lane], u2, fmaf(m1[4*BT+lane], u1, m1[3*BT+lane] * u0));
                float t2 = fmaf(m1[8*BT+lane], u2, fmaf(m1[7*BT+lane], u1, m1[6*BT+lane] * u0));
                u0 = t0; u1 = t1; u2 = t2;
            }
            // replay: stage again (L2-hot) and apply vectors
            float v0 = u0, v1 = u1, v2 = u2;
            stage4(bufs[0], R4 + ((jb * 9) >> 2), t9q, lane); CP_COMMIT();
            for (int cc = 0; cc < 4; cc++) {
                if (cc < 3) { stage4(bufs[(cc+1)&1], R4 + (((jb - 4*(cc+1)) * 9) >> 2), t9q, lane); CP_COMMIT(); CP_WAIT1(); }
                else CP_WAIT0();
                __syncwarp();
                const float4* buf = bufs[cc & 1];
#pragma unroll
                for (int sub = 0; sub < 4; sub++) {
                    float A[9];
                    switch (sub) {
                        case 0: loadA4<3>(A, buf, lane); break;
                        case 1: loadA4<2>(A, buf, lane); break;
                        case 2: loadA4<1>(A, buf, lane); break;
                        default: loadA4<0>(A, buf, lane); break;
                    }
                    float n0 = fmaf(A[6], v2, fmaf(A[3], v1, A[0] * v0));
                    float n1 = fmaf(A[7], v2, fmaf(A[4], v1, A[1] * v0));
                    float n2 = fmaf(A[8], v2, fmaf(A[5], v1, A[2] * v0));
                    v0 = n0; v1 = n1; v2 = n2;
                    const int r = 3 * (16*s + 4*cc + sub);
                    xr[(r+0) * BT + (lane ^ ((r+0) & 31))] = v0;
                    xr[(r+1) * BT + (lane ^ ((r+1) & 31))] = v1;
                    xr[(r+2) * BT + (lane ^ ((r+2) & 31))] = v2;
                }
            }
            __syncwarp();
            storeX48(oblk + (size_t)(16*s) * 3, T3, xr + 48*s * BT, (48*s) & 31, lane);
            __syncthreads();   // sync2
        } else {
            // ---- w3: prefix u3 = M2*M1*v15; writes rows 0..15; replay seg3 ----
            __syncthreads();   // sync1

            float u0 = xr[45 * BT + (lane ^ 13)];
            float u1 = xr[46 * BT + (lane ^ 14)];
            float u2 = xr[47 * BT + (lane ^ 15)];
            {
                const float* m1 = mm;
                float t0 = fmaf(m1[2*BT+lane], u2, fmaf(m1[1*BT+lane], u1, m1[0*BT+lane] * u0));
                float t1 = fmaf(m1[5*BT+lane], u2, fmaf(m1[4*BT+lane], u1, m1[3*BT+lane] * u0));
                float t2 = fmaf(m1[8*BT+lane], u2, fmaf(m1[7*BT+lane], u1, m1[6*BT+lane] * u0));
                const float* m2 = mm + 9 * BT;
                u0 = fmaf(m2[2*BT+lane], t2, fmaf(m2[1*BT+lane], t1, m2[0*BT+lane] * t0));
                u1 = fmaf(m2[5*BT+lane], t2, fmaf(m2[4*BT+lane], t1, m2[3*BT+lane] * t0));
                u2 = fmaf(m2[8*BT+lane], t2, fmaf(m2[7*BT+lane], t1, m2[6*BT+lane] * t0));
            }
            const int jb = 60 - 48;                // seg3: j0 = 12 - 4cc
            stage4(bufs[0], R4 + ((jb * 9) >> 2), t9q, lane); CP_COMMIT();
            storeX48(oblk, T3, xr, 0, lane);       // rows 0..15 (w0's, post-sync1)
            float v0 = u0, v1 = u1, v2 = u2;
            for (int cc = 0; cc < 4; cc++) {
                if (cc < 3) { stage4(bufs[(cc+1)&1], R4 + (((jb - 4*(cc+1)) * 9) >> 2), t9q, lane); CP_COMMIT(); CP_WAIT1(); }
                else CP_WAIT0();
                __syncwarp();
                const float4* buf = bufs[cc & 1];
#pragma unroll
                for (int sub = 0; sub < 4; sub++) {
                    float A[9];
                    switch (sub) {
                        case 0: loadA4<3>(A, buf, lane); break;
                        case 1: loadA4<2>(A, buf, lane); break;
                        case 2: loadA4<1>(A, buf, lane); break;
                        default: loadA4<0>(A, buf, lane); break;
                    }
                    float n0 = fmaf(A[6], v2, fmaf(A[3], v1, A[0] * v0));
                    float n1 = fmaf(A[7], v2, fmaf(A[4], v1, A[1] * v0));
                    float n2 = fmaf(A[8], v2, fmaf(A[5], v1, A[2] * v0));
                    v0 = n0; v1 = n1; v2 = n2;
                    const int r = 3 * (48 + 4*cc + sub);
                    xr[(r+0) * BT + (lane ^ ((r+0) & 31))] = v0;
                    xr[(r+1) * BT + (lane ^ ((r+1) & 31))] = v1;
                    xr[(r+2) * BT + (lane ^ ((r+2) & 31))] = v2;
                }
            }
            __syncwarp();
            storeX48(oblk + (size_t)48 * 3, T3, xr + 144 * BT, 144 & 31, lane);
            __syncthreads();   // sync2
        }
    } else {
        // ================= FWD block: 4 independent warps x 32 b's =================
        const int bbase = ((int)blockIdx.x - nbackblk) * 128 + w * BT;
        const float4* R4 = (const float4*)R + (size_t)bbase * t9q;
        float* oblk = out + (size_t)bbase * T3;
        float4* buf0 = (float4*)(smem + w * 10752);
        float4* buf1 = buf0 + 288;
        float4* bufs[2] = { buf0, buf1 };
        float* sout = (float*)(smem + w * 10752 + 9216);
        const int nsteps = T - 1 - half;           // 63
        const int nchunks = 16;

        float v0 = __ldg(dir + (size_t)(bbase + lane) * 3 + 0);
        float v1 = __ldg(dir + (size_t)(bbase + lane) * 3 + 1);
        float v2 = __ldg(dir + (size_t)(bbase + lane) * 3 + 2);

        stage4(bufs[0], R4 + ((half * 9) >> 2), t9q, lane); CP_COMMIT();
        for (int cc = 0; cc < nchunks; cc++) {
            if (cc + 1 < nchunks) {
                stage4(bufs[(cc+1)&1], R4 + (((half + 4*(cc+1)) * 9) >> 2), t9q, lane);
                CP_COMMIT(); CP_WAIT1();
            } else CP_WAIT0();
            __syncwarp();

            const float4* buf = bufs[cc & 1];
            const int ns = (nsteps - 4*cc) < 4 ? (nsteps - 4*cc) : 4;
#pragma unroll
            for (int sub = 0; sub < 4; sub++) {
                if (sub < ns) {
                    float A[9];
                    switch (sub) {
                        case 0: loadA4<0>(A, buf, lane); break;
                        case 1: loadA4<1>(A, buf, lane); break;
                        case 2: loadA4<2>(A, buf, lane); break;
                        default: loadA4<3>(A, buf, lane); break;
                    }
                    float n0 = fmaf(A[2], v2, fmaf(A[1], v1, A[0] * v0));
                    float n1 = fmaf(A[5], v2, fmaf(A[4], v1, A[3] * v0));
                    float n2 = fmaf(A[8], v2, fmaf(A[7], v1, A[6] * v0));
                    v0 = n0; v1 = n1; v2 = n2;
                    const int eo = 3 * sub;
                    sout[(eo+0) * BT + (lane ^ (eo+0))] = v0;
                    sout[(eo+1) * BT + (lane ^ (eo+1))] = v1;
                    sout[(eo+2) * BT + (lane ^ (eo+2))] = v2;
                }
            }
            __syncwarp();
            float* gdst = oblk + (size_t)(half + 1 + 4*cc) * 3;
            if (ns == 4) store_chain<12>(gdst, T3, sout, lane);
            else         store_chain<9>(gdst, T3, sout, lane);
            __syncwarp();
        }
    }
}

extern "C" void kernel_launch(void* const* d_in, const int* in_sizes, int n_in,
                              void* d_out, int out_size)
{
    const float* dir = (const float*)d_in[0];
    const float* R   = (const float*)d_in[1];
    const float* Wih = (const float*)d_in[2];
    const float* Whh = (const float*)d_in[3];
    const float* bih = (const float*)d_in[4];
    const float* bhh = (const float*)d_in[5];
    float* out = (float*)d_out;

    const int B = in_sizes[0] / 3;
    const int T = in_sizes[1] / (B * 9);
    const int nbackblk = B / 32;    // 512
    const int nfwdblk  = B / 128;   // 128

    static int attr_set = 0;
    if (!attr_set) {
        cudaFuncSetAttribute(gaze_kernel, cudaFuncAttributeMaxDynamicSharedMemorySize, SMEM_DYN);
        attr_set = 1;
    }
    gaze_kernel<<<nbackblk + nfwdblk, 128, SMEM_DYN>>>(dir, R, Wih, Whh, bih, bhh, out, B, T, nbackblk);
}

// round 12
// speedup vs baseline: 1.8595x; 1.8595x over previous
#include <cuda_runtime.h>
#include <cstddef>

// GazeLSTM on GB300 (sm_103a). B=16384, T=128, half=64.
// Single kernel, 32-thread (1-warp) blocks (R9 structure, spill-free fused branch):
//  * blocks [0, nback): backward chain + FUSED LSTM. Inner loop 2x4 (outer not
//    unrolled) to cap live ranges; ALL LSTM weights in volatile SMEM (no weight
//    registers). Writes rows 0..half-1 and row half.
//  * blocks [nback, ..): forward chain (unchanged). Writes rows half+1..T-1.

#define BT  32      // b's per block (one warp)
#define C   8       // matrices per chunk
#define NQ  18      // float4 per b per chain chunk

__device__ __forceinline__ unsigned long long pk2(float lo, float hi) {
    unsigned long long r; asm("mov.b64 %0, {%1, %2};" : "=l"(r) : "f"(lo), "f"(hi)); return r;
}
__device__ __forceinline__ void upk2(float& lo, float& hi, unsigned long long v) {
    asm("mov.b64 {%0, %1}, %2;" : "=f"(lo), "=f"(hi) : "l"(v));
}
__device__ __forceinline__ unsigned long long fma2(unsigned long long a, unsigned long long b, unsigned long long c) {
    unsigned long long d; asm("fma.rn.f32x2 %0, %1, %2, %3;" : "=l"(d) : "l"(a), "l"(b), "l"(c)); return d;
}
__device__ __forceinline__ float tanhx(float x) {
    float y; asm("tanh.approx.f32 %0, %1;" : "=f"(y) : "f"(x)); return y;
}

#define CP16(dst_u32, src_ptr) \
    asm volatile("cp.async.cg.shared.global [%0], [%1], 16;" :: "r"(dst_u32), "l"(src_ptr))
#define CP_COMMIT() asm volatile("cp.async.commit_group;")
#define CP_WAIT1()  asm volatile("cp.async.wait_group 1;")
#define CP_WAIT0()  asm volatile("cp.async.wait_group 0;")

// Stage chain chunk: 32 b's x NQ quads, 18 CP16/thread. j0 % 4 == 0 required.
__device__ __forceinline__ void stage_chain(float4* __restrict__ sdst,
                                            const float4* __restrict__ src4base,
                                            int t9q, int tid) {
    int bp = tid / NQ;
    int q  = tid - bp * NQ;
#pragma unroll
    for (int k = 0; k < NQ; k++) {
        const float4* src = src4base + (size_t)bp * t9q + q;
        unsigned dst = (unsigned)__cvta_generic_to_shared(sdst + q * BT + (bp ^ q));
        CP16(dst, src);
        q += 14; bp += 1;                 // advance 32 = 1*18 + 14
        if (q >= NQ) { q -= NQ; bp += 1; }
    }
}

// Compile-time M (forward branch, unchanged from R9).
template <int M>
__device__ __forceinline__ void loadA(float* A, const float4* __restrict__ buf, int tid) {
    constexpr int F0 = 9 * M, QA = F0 >> 2, OFF = F0 & 3;
    float tmp[12];
    *(float4*)(tmp + 0) = buf[(QA + 0) * BT + (tid ^ (QA + 0))];
    *(float4*)(tmp + 4) = buf[(QA + 1) * BT + (tid ^ (QA + 1))];
    *(float4*)(tmp + 8) = buf[(QA + 2) * BT + (tid ^ (QA + 2))];
#pragma unroll
    for (int i = 0; i < 9; i++) A[i] = tmp[OFF + i];
}

// Runtime quad base (qa < 16), compile-time byte offset within first quad.
template <int OFF>
__device__ __forceinline__ void loadA_r(float* A, const float4* __restrict__ buf,
                                        int qa, int tid) {
    float tmp[12];
    *(float4*)(tmp + 0) = buf[(qa + 0) * BT + (tid ^ (qa + 0))];
    *(float4*)(tmp + 4) = buf[(qa + 1) * BT + (tid ^ (qa + 1))];
    *(float4*)(tmp + 8) = buf[(qa + 2) * BT + (tid ^ (qa + 2))];
#pragma unroll
    for (int i = 0; i < 9; i++) A[i] = tmp[OFF + i];
}

// Coalesced writeback: NF floats/b for 32 b's from swizzled sout.
template <int NF>
__device__ __forceinline__ void store_chain(float* __restrict__ gdst, size_t T3,
                                            const float* __restrict__ sout, int tid) {
    int bp = tid / NF;
    int e  = tid - bp * NF;
    constexpr int DB = BT / NF;
    constexpr int DE = BT % NF;
#pragma unroll
    for (int k = 0; k < NF; k++) {
        gdst[(size_t)bp * T3 + e] = sout[e * BT + (bp ^ e)];
        bp += DB; e += DE;
        if (e >= NF) { e -= NF; bp += 1; }
    }
}

// LSTM step, ALL weights via volatile smem (prescaled: sigmoid gates x0.5;
// sig(x)=0.5+0.5*tanh(x/2)). vw layout per p: [0..2]=WI, [3..5]=WH, [6]=bias.
#define LSTM_STEP_SW(x0, x1, x2)                                                     \
    do {                                                                             \
        unsigned long long xx0 = pk2((x0), (x0)), xx1 = pk2((x1), (x1)), xx2 = pk2((x2), (x2)); \
        unsigned long long hh0 = pk2(h0, h0), hh1 = pk2(h1, h1), hh2 = pk2(h2, h2);  \
        float th[12];                                                                \
        _Pragma("unroll") for (int p = 0; p < 6; p++) {                              \
            unsigned long long xp = fma2(vw[p*7+0], xx0, fma2(vw[p*7+1], xx1, fma2(vw[p*7+2], xx2, vw[p*7+6]))); \
            unsigned long long g  = fma2(vw[p*7+3], hh0, fma2(vw[p*7+4], hh1, fma2(vw[p*7+5], hh2, xp)));        \
            float a_, b_; upk2(a_, b_, g);                                           \
            th[2*p] = tanhx(a_); th[2*p+1] = tanhx(b_);                              \
        }                                                                            \
        float i0 = fmaf(0.5f, th[0], 0.5f), i1 = fmaf(0.5f, th[1], 0.5f), i2 = fmaf(0.5f, th[2], 0.5f); \
        float f0 = fmaf(0.5f, th[3], 0.5f), f1 = fmaf(0.5f, th[4], 0.5f), f2 = fmaf(0.5f, th[5], 0.5f); \
        float o0 = fmaf(0.5f, th[9], 0.5f), o1 = fmaf(0.5f, th[10], 0.5f), o2 = fmaf(0.5f, th[11], 0.5f); \
        c0 = fmaf(f0, c0, i0 * th[6]);                                               \
        c1 = fmaf(f1, c1, i1 * th[7]);                                               \
        c2 = fmaf(f2, c2, i2 * th[8]);                                               \
        h0 = o0 * tanhx(c0); h1 = o1 * tanhx(c1); h2 = o2 * tanhx(c2);               \
    } while (0)

__global__ __launch_bounds__(BT, 12) void gaze_kernel(
    const float* __restrict__ dir, const float* __restrict__ R,
    const float* __restrict__ Wih, const float* __restrict__ Whh,
    const float* __restrict__ bih, const float* __restrict__ bhh,
    float* __restrict__ out, int B, int T, int nback)
{
    __shared__ float4 sbuf[2][NQ * BT];           // 2 x 9216 B
    __shared__ float  sout[3 * C * BT];           // 3072 B
    __shared__ unsigned long long swts[42];       // 336 B (fused blocks only)

    const int half = T >> 1;
    const int t9q = (T * 9) >> 2;
    const size_t T3 = (size_t)T * 3;
    const int tid = threadIdx.x;
    const int nchunks = half / C;                 // 8

    if ((int)blockIdx.x < nback) {
        // ============ fused backward chain + LSTM: 32 b's ============
        const int bbase = blockIdx.x * BT;

        // SMEM weight init: 6 threads, one gate-pair each (prescaled, packed).
        if (tid < 6) {
            const int p = tid, g0 = 2 * p, g1 = 2 * p + 1;
            const float s0 = (g0 >= 6 && g0 <= 8) ? 1.0f : 0.5f;
            const float s1 = (g1 >= 6 && g1 <= 8) ? 1.0f : 0.5f;
#pragma unroll
            for (int j = 0; j < 3; j++) {
                swts[p*7 + j]     = pk2(__ldg(Wih + g0*3 + j) * s0, __ldg(Wih + g1*3 + j) * s1);
                swts[p*7 + 3 + j] = pk2(__ldg(Whh + g0*3 + j) * s0, __ldg(Whh + g1*3 + j) * s1);
            }
            swts[p*7 + 6] = pk2((__ldg(bih + g0) + __ldg(bhh + g0)) * s0,
                                (__ldg(bih + g1) + __ldg(bhh + g1)) * s1);
        }
        const volatile unsigned long long* vw = swts;

        const float d0 = __ldg(dir + (size_t)(bbase + tid) * 3 + 0);
        const float d1 = __ldg(dir + (size_t)(bbase + tid) * 3 + 1);
        const float d2 = __ldg(dir + (size_t)(bbase + tid) * 3 + 2);
        float v0 = d0, v1 = d1, v2 = d2;
        float h0 = 0.f, h1 = 0.f, h2 = 0.f, c0 = 0.f, c1 = 0.f, c2 = 0.f;

        const float4* R4 = (const float4*)R + (size_t)bbase * t9q;
        float* oblk = out + (size_t)bbase * T3;

        stage_chain(sbuf[0], R4 + (((half - C) * 9) >> 2), t9q, tid);
        CP_COMMIT();
        __syncwarp();                              // weights visible

        for (int cc = 0; cc < nchunks; cc++) {
            if (cc + 1 < nchunks) {
                stage_chain(sbuf[(cc + 1) & 1], R4 + (((half - C * (cc + 2)) * 9) >> 2), t9q, tid);
                CP_COMMIT(); CP_WAIT1();
            } else CP_WAIT0();
            __syncwarp();

            const float4* buf = sbuf[cc & 1];
            // steps s = 4j+k use matrix M = 7-s:  F0 = 63-36j-9k,
            // QA = {15,13,11,9}[k] - 9j (exact: 36j % 4 == 0), OFF = {3,2,1,0}[k].
#pragma unroll 1
            for (int j = 0; j < 2; j++) {
                const int qb = 9 * j;
                int eo = 12 * j;                   // sout element base = 3*(4j)
#pragma unroll
                for (int k = 0; k < 4; k++) {
                    float A[9];
                    switch (k) {
                        case 0:  loadA_r<3>(A, buf, 15 - qb, tid); break;
                        case 1:  loadA_r<2>(A, buf, 13 - qb, tid); break;
                        case 2:  loadA_r<1>(A, buf, 11 - qb, tid); break;
                        default: loadA_r<0>(A, buf,  9 - qb, tid); break;
                    }
                    // v = A^T v
                    float n0 = fmaf(A[6], v2, fmaf(A[3], v1, A[0] * v0));
                    float n1 = fmaf(A[7], v2, fmaf(A[4], v1, A[1] * v0));
                    float n2 = fmaf(A[8], v2, fmaf(A[5], v1, A[2] * v0));
                    v0 = n0; v1 = n1; v2 = n2;
                    sout[(eo + 0) * BT + (tid ^ (eo + 0))] = v0;
                    sout[(eo + 1) * BT + (tid ^ (eo + 1))] = v1;
                    sout[(eo + 2) * BT + (tid ^ (eo + 2))] = v2;
                    eo += 3;

                    LSTM_STEP_SW(v0, v1, v2);      // consumes x_t = dirs[8cc+4j+k]
                }
            }
            __syncwarp();
            store_chain<3 * C>(oblk + (size_t)(C * cc) * 3, T3, sout, tid);
            __syncwarp();
        }

        // final LSTM step consumes dir; h is the output row at t = half
        LSTM_STEP_SW(d0, d1, d2);
        float* ob = out + (size_t)(bbase + tid) * T3 + (size_t)half * 3;
        ob[0] = h0; ob[1] = h1; ob[2] = h2;
    } else {
        // ============ forward chain: 32 b's (R9-proven, unchanged) ============
        const int bbase = ((int)blockIdx.x - nback) * BT;
        const int nsteps = T - 1 - half;           // 63

        float v0 = __ldg(dir + (size_t)(bbase + tid) * 3 + 0);
        float v1 = __ldg(dir + (size_t)(bbase + tid) * 3 + 1);
        float v2 = __ldg(dir + (size_t)(bbase + tid) * 3 + 2);

        const float4* R4 = (const float4*)R + (size_t)bbase * t9q;
        float* oblk = out + (size_t)bbase * T3;

        stage_chain(sbuf[0], R4 + ((half * 9) >> 2), t9q, tid);
        CP_COMMIT();
        for (int cc = 0; cc < nchunks; cc++) {
            if (cc + 1 < nchunks) {
                stage_chain(sbuf[(cc + 1) & 1], R4 + (((half + C * (cc + 1)) * 9) >> 2), t9q, tid);
                CP_COMMIT(); CP_WAIT1();
            } else CP_WAIT0();
            __syncwarp();

            const float4* buf = sbuf[cc & 1];
            const int ns = (nsteps - C * cc) < C ? (nsteps - C * cc) : C;
#pragma unroll
            for (int s = 0; s < C; s++) {
                if (s < ns) {
                    float A[9];
                    switch (s) {
                        case 0: loadA<0>(A, buf, tid); break;
                        case 1: loadA<1>(A, buf, tid); break;
                        case 2: loadA<2>(A, buf, tid); break;
                        case 3: loadA<3>(A, buf, tid); break;
                        case 4: loadA<4>(A, buf, tid); break;
                        case 5: loadA<5>(A, buf, tid); break;
                        case 6: loadA<6>(A, buf, tid); break;
                        default: loadA<7>(A, buf, tid); break;
                    }
                    // v = A v
                    float n0 = fmaf(A[2], v2, fmaf(A[1], v1, A[0] * v0));
                    float n1 = fmaf(A[5], v2, fmaf(A[4], v1, A[3] * v0));
                    float n2 = fmaf(A[8], v2, fmaf(A[7], v1, A[6] * v0));
                    v0 = n0; v1 = n1; v2 = n2;
                    const int eo = 3 * s;
                    sout[(eo + 0) * BT + (tid ^ (eo + 0))] = v0;
                    sout[(eo + 1) * BT + (tid ^ (eo + 1))] = v1;
                    sout[(eo + 2) * BT + (tid ^ (eo + 2))] = v2;
                }
            }
            __syncwarp();
            float* gdst = oblk + (size_t)(half + 1 + C * cc) * 3;
            if (ns == C) store_chain<3 * C>(gdst, T3, sout, tid);
            else         store_chain<21>(gdst, T3, sout, tid);   // last: 7 steps
            __syncwarp();
        }
    }
}

extern "C" void kernel_launch(void* const* d_in, const int* in_sizes, int n_in,
                              void* d_out, int out_size)
{
    const float* dir = (const float*)d_in[0];
    const float* R   = (const float*)d_in[1];
    const float* Wih = (const float*)d_in[2];
    const float* Whh = (const float*)d_in[3];
    const float* bih = (const float*)d_in[4];
    const float* bhh = (const float*)d_in[5];
    float* out = (float*)d_out;

    const int B = in_sizes[0] / 3;
    const int T = in_sizes[1] / (B * 9);
    const int nback = B / BT;   // 512
    const int nfwd  = B / BT;   // 512

    gaze_kernel<<<nback + nfwd, BT>>>(dir, R, Wih, Whh, bih, bhh, out, B, T, nback);
}

// round 13
// speedup vs baseline: 2.1036x; 1.1313x over previous
#include <cuda_runtime.h>
#include <cstddef>

// GazeLSTM on GB300 (sm_103a). B=16384, T=128, half=64.
// Single kernel, 32-thread (1-warp) blocks:
//  * blocks [0, nback): backward chain + FUSED LSTM. Lean 2x4 inner loop
//    (caps live ranges) + ALL 42 packed weights in registers (one-shot __ldg,
//    zero per-step weight loads). Writes rows 0..half-1 and row half.
//  * blocks [nback, ..): forward chain (unchanged). Writes rows half+1..T-1.

#define BT  32      // b's per block (one warp)
#define C   8       // matrices per chunk
#define NQ  18      // float4 per b per chain chunk

__device__ __forceinline__ unsigned long long pk2(float lo, float hi) {
    unsigned long long r; asm("mov.b64 %0, {%1, %2};" : "=l"(r) : "f"(lo), "f"(hi)); return r;
}
__device__ __forceinline__ void upk2(float& lo, float& hi, unsigned long long v) {
    asm("mov.b64 {%0, %1}, %2;" : "=f"(lo), "=f"(hi) : "l"(v));
}
__device__ __forceinline__ unsigned long long fma2(unsigned long long a, unsigned long long b, unsigned long long c) {
    unsigned long long d; asm("fma.rn.f32x2 %0, %1, %2, %3;" : "=l"(d) : "l"(a), "l"(b), "l"(c)); return d;
}
__device__ __forceinline__ float tanhx(float x) {
    float y; asm("tanh.approx.f32 %0, %1;" : "=f"(y) : "f"(x)); return y;
}

#define CP16(dst_u32, src_ptr) \
    asm volatile("cp.async.cg.shared.global [%0], [%1], 16;" :: "r"(dst_u32), "l"(src_ptr))
#define CP_COMMIT() asm volatile("cp.async.commit_group;")
#define CP_WAIT1()  asm volatile("cp.async.wait_group 1;")
#define CP_WAIT0()  asm volatile("cp.async.wait_group 0;")

// Stage chain chunk: 32 b's x NQ quads, 18 CP16/thread. j0 % 4 == 0 required.
__device__ __forceinline__ void stage_chain(float4* __restrict__ sdst,
                                            const float4* __restrict__ src4base,
                                            int t9q, int tid) {
    int bp = tid / NQ;
    int q  = tid - bp * NQ;
#pragma unroll
    for (int k = 0; k < NQ; k++) {
        const float4* src = src4base + (size_t)bp * t9q + q;
        unsigned dst = (unsigned)__cvta_generic_to_shared(sdst + q * BT + (bp ^ q));
        CP16(dst, src);
        q += 14; bp += 1;                 // advance 32 = 1*18 + 14
        if (q >= NQ) { q -= NQ; bp += 1; }
    }
}

// Compile-time M (forward branch).
template <int M>
__device__ __forceinline__ void loadA(float* A, const float4* __restrict__ buf, int tid) {
    constexpr int F0 = 9 * M, QA = F0 >> 2, OFF = F0 & 3;
    float tmp[12];
    *(float4*)(tmp + 0) = buf[(QA + 0) * BT + (tid ^ (QA + 0))];
    *(float4*)(tmp + 4) = buf[(QA + 1) * BT + (tid ^ (QA + 1))];
    *(float4*)(tmp + 8) = buf[(QA + 2) * BT + (tid ^ (QA + 2))];
#pragma unroll
    for (int i = 0; i < 9; i++) A[i] = tmp[OFF + i];
}

// Runtime quad base (qa < 16), compile-time byte offset within first quad.
template <int OFF>
__device__ __forceinline__ void loadA_r(float* A, const float4* __restrict__ buf,
                                        int qa, int tid) {
    float tmp[12];
    *(float4*)(tmp + 0) = buf[(qa + 0) * BT + (tid ^ (qa + 0))];
    *(float4*)(tmp + 4) = buf[(qa + 1) * BT + (tid ^ (qa + 1))];
    *(float4*)(tmp + 8) = buf[(qa + 2) * BT + (tid ^ (qa + 2))];
#pragma unroll
    for (int i = 0; i < 9; i++) A[i] = tmp[OFF + i];
}

// Coalesced writeback: NF floats/b for 32 b's from swizzled sout.
template <int NF>
__device__ __forceinline__ void store_chain(float* __restrict__ gdst, size_t T3,
                                            const float* __restrict__ sout, int tid) {
    int bp = tid / NF;
    int e  = tid - bp * NF;
    constexpr int DB = BT / NF;
    constexpr int DE = BT % NF;
#pragma unroll
    for (int k = 0; k < NF; k++) {
        gdst[(size_t)bp * T3 + e] = sout[e * BT + (bp ^ e)];
        bp += DB; e += DE;
        if (e >= NF) { e -= NF; bp += 1; }
    }
}

// LSTM step, register weights (prescaled: sigmoid gates x0.5;
// sig(x)=0.5+0.5*tanh(x/2)).
#define LSTM_STEP(x0, x1, x2)                                                        \
    do {                                                                             \
        unsigned long long xx0 = pk2((x0), (x0)), xx1 = pk2((x1), (x1)), xx2 = pk2((x2), (x2)); \
        unsigned long long hh0 = pk2(h0, h0), hh1 = pk2(h1, h1), hh2 = pk2(h2, h2);  \
        float th[12];                                                                \
        _Pragma("unroll") for (int p = 0; p < 6; p++) {                              \
            unsigned long long xp = fma2(WI[p][0], xx0, fma2(WI[p][1], xx1, fma2(WI[p][2], xx2, BS[p]))); \
            unsigned long long g  = fma2(WH[p][0], hh0, fma2(WH[p][1], hh1, fma2(WH[p][2], hh2, xp)));    \
            float a_, b_; upk2(a_, b_, g);                                           \
            th[2*p] = tanhx(a_); th[2*p+1] = tanhx(b_);                              \
        }                                                                            \
        float i0 = fmaf(0.5f, th[0], 0.5f), i1 = fmaf(0.5f, th[1], 0.5f), i2 = fmaf(0.5f, th[2], 0.5f); \
        float f0 = fmaf(0.5f, th[3], 0.5f), f1 = fmaf(0.5f, th[4], 0.5f), f2 = fmaf(0.5f, th[5], 0.5f); \
        float o0 = fmaf(0.5f, th[9], 0.5f), o1 = fmaf(0.5f, th[10], 0.5f), o2 = fmaf(0.5f, th[11], 0.5f); \
        c0 = fmaf(f0, c0, i0 * th[6]);                                               \
        c1 = fmaf(f1, c1, i1 * th[7]);                                               \
        c2 = fmaf(f2, c2, i2 * th[8]);                                               \
        h0 = o0 * tanhx(c0); h1 = o1 * tanhx(c1); h2 = o2 * tanhx(c2);               \
    } while (0)

__global__ __launch_bounds__(BT) void gaze_kernel(
    const float* __restrict__ dir, const float* __restrict__ R,
    const float* __restrict__ Wih, const float* __restrict__ Whh,
    const float* __restrict__ bih, const float* __restrict__ bhh,
    float* __restrict__ out, int B, int T, int nback)
{
    __shared__ float4 sbuf[2][NQ * BT];           // 2 x 9216 B
    __shared__ float  sout[3 * C * BT];           // 3072 B

    const int half = T >> 1;
    const int t9q = (T * 9) >> 2;
    const size_t T3 = (size_t)T * 3;
    const int tid = threadIdx.x;
    const int nchunks = half / C;                 // 8

    if ((int)blockIdx.x < nback) {
        // ============ fused backward chain + LSTM: 32 b's ============
        const int bbase = blockIdx.x * BT;

        // one-shot register weights (prescaled, packed f32x2)
        unsigned long long WI[6][3], WH[6][3], BS[6];
#pragma unroll
        for (int p = 0; p < 6; p++) {
            const int g0 = 2 * p, g1 = 2 * p + 1;
            const float s0 = (g0 >= 6 && g0 <= 8) ? 1.0f : 0.5f;
            const float s1 = (g1 >= 6 && g1 <= 8) ? 1.0f : 0.5f;
#pragma unroll
            for (int j = 0; j < 3; j++) {
                WI[p][j] = pk2(__ldg(Wih + g0*3 + j) * s0, __ldg(Wih + g1*3 + j) * s1);
                WH[p][j] = pk2(__ldg(Whh + g0*3 + j) * s0, __ldg(Whh + g1*3 + j) * s1);
            }
            BS[p] = pk2((__ldg(bih + g0) + __ldg(bhh + g0)) * s0,
                        (__ldg(bih + g1) + __ldg(bhh + g1)) * s1);
        }

        const float d0 = __ldg(dir + (size_t)(bbase + tid) * 3 + 0);
        const float d1 = __ldg(dir + (size_t)(bbase + tid) * 3 + 1);
        const float d2 = __ldg(dir + (size_t)(bbase + tid) * 3 + 2);
        float v0 = d0, v1 = d1, v2 = d2;
        float h0 = 0.f, h1 = 0.f, h2 = 0.f, c0 = 0.f, c1 = 0.f, c2 = 0.f;

        const float4* R4 = (const float4*)R + (size_t)bbase * t9q;
        float* oblk = out + (size_t)bbase * T3;

        stage_chain(sbuf[0], R4 + (((half - C) * 9) >> 2), t9q, tid);
        CP_COMMIT();

        for (int cc = 0; cc < nchunks; cc++) {
            if (cc + 1 < nchunks) {
                stage_chain(sbuf[(cc + 1) & 1], R4 + (((half - C * (cc + 2)) * 9) >> 2), t9q, tid);
                CP_COMMIT(); CP_WAIT1();
            } else CP_WAIT0();
            __syncwarp();

            const float4* buf = sbuf[cc & 1];
            // steps s = 4j+k use matrix M = 7-s:  F0 = 63-36j-9k,
            // QA = {15,13,11,9}[k] - 9j (exact: 36j % 4 == 0), OFF = {3,2,1,0}[k].
#pragma unroll 1
            for (int j = 0; j < 2; j++) {
                const int qb = 9 * j;
                int eo = 12 * j;                   // sout element base = 3*(4j)
#pragma unroll
                for (int k = 0; k < 4; k++) {
                    float A[9];
                    switch (k) {
                        case 0:  loadA_r<3>(A, buf, 15 - qb, tid); break;
                        case 1:  loadA_r<2>(A, buf, 13 - qb, tid); break;
                        case 2:  loadA_r<1>(A, buf, 11 - qb, tid); break;
                        default: loadA_r<0>(A, buf,  9 - qb, tid); break;
                    }
                    // v = A^T v
                    float n0 = fmaf(A[6], v2, fmaf(A[3], v1, A[0] * v0));
                    float n1 = fmaf(A[7], v2, fmaf(A[4], v1, A[1] * v0));
                    float n2 = fmaf(A[8], v2, fmaf(A[5], v1, A[2] * v0));
                    v0 = n0; v1 = n1; v2 = n2;
                    sout[(eo + 0) * BT + (tid ^ (eo + 0))] = v0;
                    sout[(eo + 1) * BT + (tid ^ (eo + 1))] = v1;
                    sout[(eo + 2) * BT + (tid ^ (eo + 2))] = v2;
                    eo += 3;

                    LSTM_STEP(v0, v1, v2);         // consumes x_t = dirs[8cc+4j+k]
                }
            }
            __syncwarp();
            store_chain<3 * C>(oblk + (size_t)(C * cc) * 3, T3, sout, tid);
            __syncwarp();
        }

        // final LSTM step consumes dir; h is the output row at t = half
        LSTM_STEP(d0, d1, d2);
        float* ob = out + (size_t)(bbase + tid) * T3 + (size_t)half * 3;
        ob[0] = h0; ob[1] = h1; ob[2] = h2;
    } else {
        // ============ forward chain: 32 b's (R9-proven, unchanged) ============
        const int bbase = ((int)blockIdx.x - nback) * BT;
        const int nsteps = T - 1 - half;           // 63

        float v0 = __ldg(dir + (size_t)(bbase + tid) * 3 + 0);
        float v1 = __ldg(dir + (size_t)(bbase + tid) * 3 + 1);
        float v2 = __ldg(dir + (size_t)(bbase + tid) * 3 + 2);

        const float4* R4 = (const float4*)R + (size_t)bbase * t9q;
        float* oblk = out + (size_t)bbase * T3;

        stage_chain(sbuf[0], R4 + ((half * 9) >> 2), t9q, tid);
        CP_COMMIT();
        for (int cc = 0; cc < nchunks; cc++) {
            if (cc + 1 < nchunks) {
                stage_chain(sbuf[(cc + 1) & 1], R4 + (((half + C * (cc + 1)) * 9) >> 2), t9q, tid);
                CP_COMMIT(); CP_WAIT1();
            } else CP_WAIT0();
            __syncwarp();

            const float4* buf = sbuf[cc & 1];
            const int ns = (nsteps - C * cc) < C ? (nsteps - C * cc) : C;
#pragma unroll
            for (int s = 0; s < C; s++) {
                if (s < ns) {
                    float A[9];
                    switch (s) {
                        case 0: loadA<0>(A, buf, tid); break;
                        case 1: loadA<1>(A, buf, tid); break;
                        case 2: loadA<2>(A, buf, tid); break;
                        case 3: loadA<3>(A, buf, tid); break;
                        case 4: loadA<4>(A, buf, tid); break;
                        case 5: loadA<5>(A, buf, tid); break;
                        case 6: loadA<6>(A, buf, tid); break;
                        default: loadA<7>(A, buf, tid); break;
                    }
                    // v = A v
                    float n0 = fmaf(A[2], v2, fmaf(A[1], v1, A[0] * v0));
                    float n1 = fmaf(A[5], v2, fmaf(A[4], v1, A[3] * v0));
                    float n2 = fmaf(A[8], v2, fmaf(A[7], v1, A[6] * v0));
                    v0 = n0; v1 = n1; v2 = n2;
                    const int eo = 3 * s;
                    sout[(eo + 0) * BT + (tid ^ (eo + 0))] = v0;
                    sout[(eo + 1) * BT + (tid ^ (eo + 1))] = v1;
                    sout[(eo + 2) * BT + (tid ^ (eo + 2))] = v2;
                }
            }
            __syncwarp();
            float* gdst = oblk + (size_t)(half + 1 + C * cc) * 3;
            if (ns == C) store_chain<3 * C>(gdst, T3, sout, tid);
            else         store_chain<21>(gdst, T3, sout, tid);   // last: 7 steps
            __syncwarp();
        }
    }
}

extern "C" void kernel_launch(void* const* d_in, const int* in_sizes, int n_in,
                              void* d_out, int out_size)
{
    const float* dir = (const float*)d_in[0];
    const float* R   = (const float*)d_in[1];
    const float* Wih = (const float*)d_in[2];
    const float* Whh = (const float*)d_in[3];
    const float* bih = (const float*)d_in[4];
    const float* bhh = (const float*)d_in[5];
    float* out = (float*)d_out;

    const int B = in_sizes[0] / 3;
    const int T = in_sizes[1] / (B * 9);
    const int nback = B / BT;   // 512
    const int nfwd  = B / BT;   // 512

    gaze_kernel<<<nback + nfwd, BT>>>(dir, R, Wih, Whh, bih, bhh, out, B, T, nback);
}